// round 5
// baseline (speedup 1.0000x reference)
#include <cuda_runtime.h>
#include <cstdint>

// ---------------- problem constants ----------------
#define BB 2
#define SS 2048
#define DD 3584
#define HH 28
#define KVH 4
#define HDIM 128
#define NREP 7
#define MM (BB*SS)            // 4096
#define NQKV 4608             // 28*128 + 512 + 512
#define QK_SCALE 0.08838834764831845f
#define KIT (DD/32)           // 112 k-iters of BK=32

// ---------------- scratch ----------------
__device__ float g_q[(size_t)MM * DD];
__device__ float g_k[(size_t)MM * 512];
__device__ float g_v[(size_t)MM * 512];
__device__ float g_o[(size_t)MM * DD];
__device__ float g_xr[(size_t)MM * DD];        // tf32-rounded x
__device__ float g_wqkv[(size_t)NQKV * DD];    // tf32-rounded [wq;wk;wv]
__device__ float g_wor[(size_t)DD * DD];       // tf32-rounded wo

// ---------------- helpers ----------------
__device__ __forceinline__ float roundtf(float f) {
    uint32_t u;
    asm("cvt.rna.tf32.f32 %0, %1;" : "=r"(u) : "f"(f));
    return __uint_as_float(u);
}
__device__ __forceinline__ void mma_tf32(float c[4],
                                         uint32_t a0, uint32_t a1, uint32_t a2, uint32_t a3,
                                         uint32_t b0, uint32_t b1) {
    asm volatile(
        "mma.sync.aligned.m16n8k8.row.col.f32.tf32.tf32.f32 "
        "{%0,%1,%2,%3}, {%4,%5,%6,%7}, {%8,%9}, {%0,%1,%2,%3};"
        : "+f"(c[0]), "+f"(c[1]), "+f"(c[2]), "+f"(c[3])
        : "r"(a0), "r"(a1), "r"(a2), "r"(a3), "r"(b0), "r"(b1));
}
__device__ __forceinline__ void cp16(uint32_t s, const float* g) {
    asm volatile("cp.async.cg.shared.global [%0], [%1], 16;" :: "r"(s), "l"(g));
}

// ---------------- tf32 pre-round passes ----------------
__global__ __launch_bounds__(256) void round_copy_kernel(
    const float* __restrict__ src, float* __restrict__ dst, int n4)
{
    int i = blockIdx.x * blockDim.x + threadIdx.x;
    int stride = gridDim.x * blockDim.x;
    for (; i < n4; i += stride) {
        float4 v = ((const float4*)src)[i];
        v.x = roundtf(v.x); v.y = roundtf(v.y);
        v.z = roundtf(v.z); v.w = roundtf(v.w);
        ((float4*)dst)[i] = v;
    }
}

// =====================================================================
// TF32 TN GEMM: C[128,128] = A[128,K] * W[128,K]^T (+bias), K=3584.
// A,W pre-rounded to tf32 (raw bits fed to mma -> no cvt in loop).
// 128 thr = 4 warps (2x2), warp tile 64x64, BK=32 (4 k8-chunks),
// 3-stage cp.async, chunk-level double-buffered fragments.
// 2 CTAs/SM. smem/CTA = 3*36864B = 108KB.
// =====================================================================
#define BKW 36                              // padded row words
#define TILE_WORDS (128*BKW)                // 4608
#define STG_WORDS (2*TILE_WORDS)            // 9216
#define NSTG 3
#define GEMM_SMEM_BYTES (NSTG*STG_WORDS*4)  // 110592

__device__ __forceinline__ void gemm_tile(
    const float* __restrict__ A,           // (m0,0), ld = DD, tf32-rounded
    const float* __restrict__ W,           // (n0,0), ld = DD, tf32-rounded
    const float* __restrict__ bias,
    float* __restrict__ C, int ldc)
{
    extern __shared__ float smf[];
    uint32_t sbase = (uint32_t)__cvta_generic_to_shared(smf);

    const int tid  = threadIdx.x;
    const int warp = tid >> 5, lane = tid & 31;
    const int wm = warp >> 1, wn = warp & 1;
    const int g = lane >> 2, t = lane & 3;

    const float* Ag = A + (size_t)tid * DD;
    const float* Wg = W + (size_t)tid * DD;
    const uint32_t arow_off = (uint32_t)(tid * BKW) * 4;

    auto issue = [&](int stage, int it) {
        uint32_t sa = sbase + (uint32_t)stage * (STG_WORDS * 4) + arow_off;
        const float* ag = Ag + it * 32;
        const float* wg = Wg + it * 32;
#pragma unroll
        for (int c = 0; c < 8; c++) {
            cp16(sa + (uint32_t)(c * 4) * 4,                    ag + c * 4);
            cp16(sa + (uint32_t)(TILE_WORDS + c * 4) * 4,       wg + c * 4);
        }
        asm volatile("cp.async.commit_group;");
    };

    float acc[4][8][4];
#pragma unroll
    for (int mi = 0; mi < 4; mi++)
#pragma unroll
        for (int nj = 0; nj < 8; nj++)
#pragma unroll
            for (int c = 0; c < 4; c++) acc[mi][nj][c] = 0.f;

    issue(0, 0);
    issue(1, 1);

    const uint32_t* sm32 = (const uint32_t*)smf;
    int stage = 0;
    for (int it = 0; it < KIT; it++) {
        if (it + 2 < KIT) {
            asm volatile("cp.async.wait_group 1;");
        } else {
            asm volatile("cp.async.wait_group 0;");
        }
        __syncthreads();
        if (it + 2 < KIT) {
            int ns = stage + 2; if (ns >= NSTG) ns -= NSTG;
            issue(ns, it + 2);
        }
        const uint32_t* ab = sm32 + stage * STG_WORDS;
        const uint32_t* bb = ab + TILE_WORDS;

        uint32_t af[2][4][4], bf[2][8][2];
        auto loadfrag = [&](int buf, int chunk) {
            const int kk = chunk * 8;
#pragma unroll
            for (int mi = 0; mi < 4; mi++) {
                int row = wm * 64 + mi * 16 + g;
                af[buf][mi][0] = ab[row * BKW + kk + t];
                af[buf][mi][1] = ab[(row + 8) * BKW + kk + t];
                af[buf][mi][2] = ab[row * BKW + kk + t + 4];
                af[buf][mi][3] = ab[(row + 8) * BKW + kk + t + 4];
            }
#pragma unroll
            for (int nj = 0; nj < 8; nj++) {
                int rb = wn * 64 + nj * 8 + g;
                bf[buf][nj][0] = bb[rb * BKW + kk + t];
                bf[buf][nj][1] = bb[rb * BKW + kk + t + 4];
            }
        };

        loadfrag(0, 0);
#pragma unroll
        for (int c = 0; c < 4; c++) {
            if (c < 3) loadfrag((c + 1) & 1, c + 1);
            const int b = c & 1;
#pragma unroll
            for (int mi = 0; mi < 4; mi++)
#pragma unroll
                for (int nj = 0; nj < 8; nj++)
                    mma_tf32(acc[mi][nj],
                             af[b][mi][0], af[b][mi][1], af[b][mi][2], af[b][mi][3],
                             bf[b][nj][0], bf[b][nj][1]);
        }
        stage++; if (stage >= NSTG) stage = 0;
    }

#pragma unroll
    for (int mi = 0; mi < 4; mi++) {
        int row = wm * 64 + mi * 16 + g;
#pragma unroll
        for (int nj = 0; nj < 8; nj++) {
            int col = wn * 64 + nj * 8 + 2 * t;
            float b0 = bias ? bias[col] : 0.f;
            float b1 = bias ? bias[col + 1] : 0.f;
            *(float2*)(C + (size_t)row * ldc + col) =
                make_float2(acc[mi][nj][0] + b0, acc[mi][nj][1] + b1);
            *(float2*)(C + (size_t)(row + 8) * ldc + col) =
                make_float2(acc[mi][nj][2] + b0, acc[mi][nj][3] + b1);
        }
    }
}

// Fused QKV projection: grid (32, 36). by<28 -> Q, <32 -> K, else V.
__global__ __launch_bounds__(128, 2) void qkv_kernel(
    const float* __restrict__ bq,
    const float* __restrict__ bk,
    const float* __restrict__ bv)
{
    int m0 = blockIdx.x * 128;
    int by = blockIdx.y;
    const float* bias; float* C; int ldc;
    if (by < 28) {
        bias = bq + by * 128;
        C = g_q + (size_t)m0 * DD + by * 128; ldc = DD;
    } else if (by < 32) {
        bias = bk + (by - 28) * 128;
        C = g_k + (size_t)m0 * 512 + (by - 28) * 128; ldc = 512;
    } else {
        bias = bv + (by - 32) * 128;
        C = g_v + (size_t)m0 * 512 + (by - 32) * 128; ldc = 512;
    }
    gemm_tile(g_xr + (size_t)m0 * DD, g_wqkv + (size_t)by * 128 * DD,
              bias, C, ldc);
}

// Output projection: grid (32, 28). g_o already tf32-rounded in place.
__global__ __launch_bounds__(128, 2) void oproj_kernel(float* __restrict__ out)
{
    int m0 = blockIdx.x * 128;
    int n0 = blockIdx.y * 128;
    gemm_tile(g_o + (size_t)m0 * DD, g_wor + (size_t)n0 * DD, nullptr,
              out + (size_t)m0 * DD + n0, DD);
}

// =====================================================================
// RoPE on g_q and g_k (in place).
// =====================================================================
__global__ __launch_bounds__(256) void rope_kernel(
    const float* __restrict__ cosT, const float* __restrict__ sinT,
    const int* __restrict__ spp)
{
    const int QP = MM * HH * 64;
    const int KP = MM * KVH * 64;
    int idx = blockIdx.x * blockDim.x + threadIdx.x;
    if (idx >= QP + KP) return;
    int sp = spp[0];
    float* buf; int nh; int i2;
    if (idx < QP) { buf = g_q; nh = HH;  i2 = idx; }
    else          { buf = g_k; nh = KVH; i2 = idx - QP; }
    int d2 = i2 & 63;
    int t  = i2 >> 6;
    int h  = t % nh;
    int m  = t / nh;
    int s  = m & (SS - 1);
    int pos = sp + s;
    float c  = cosT[pos * 64 + d2];
    float sn = sinT[pos * 64 + d2];
    size_t off = (size_t)m * (nh * HDIM) + h * HDIM + 2 * d2;
    float2 v = *(float2*)(buf + off);
    float yr = v.x * c - v.y * sn;
    float yi = v.x * sn + v.y * c;
    *(float2*)(buf + off) = make_float2(yr, yi);
}

// =====================================================================
// Flash attention (causal), fp32. BM=128, BN=64, HD=128, 256 thr (16x16).
// (At fp32-FMA roofline; unchanged.)
// =====================================================================
#define QTP 132
#define KTP 68
#define ATTN_SMEM_WORDS (128*QTP + 128*KTP + 64*128 + 128*KTP)
#define ATTN_SMEM_BYTES (ATTN_SMEM_WORDS*4)   // 169984

__global__ __launch_bounds__(256) void attn_kernel()
{
    extern __shared__ float sm[];
    float* Qt = sm;                       // [128 d][132 rows]
    float* Kt = Qt + 128*QTP;             // [128 d][68 rows]
    float* Vs = Kt + 128*KTP;             // [64 rows][128 d]
    float* Ps = Vs + 64*128;              // [128 rows][68 cols]

    const int qt = gridDim.x - 1 - blockIdx.x;
    const int h  = blockIdx.y;
    const int b  = blockIdx.z;
    const int kvh = h / NREP;
    const int tid = threadIdx.x;
    const int ty = tid >> 4, tx = tid & 15;

    const int qrow0 = b * SS + qt * 128;

    {
        const float* qbase = g_q + (size_t)qrow0 * DD + h * HDIM;
#pragma unroll
        for (int tt = 0; tt < 16; tt++) {
            int f4 = tid + tt * 256;
            int row = f4 >> 5, d4 = f4 & 31;
            float4 qv = *(const float4*)(qbase + (size_t)row * DD + d4 * 4);
            Qt[(d4*4+0)*QTP + row] = qv.x;
            Qt[(d4*4+1)*QTP + row] = qv.y;
            Qt[(d4*4+2)*QTP + row] = qv.z;
            Qt[(d4*4+3)*QTP + row] = qv.w;
        }
    }

    float m_i[8], l_i[8], o_acc[8][8];
#pragma unroll
    for (int i = 0; i < 8; i++) {
        m_i[i] = -1e30f; l_i[i] = 0.f;
#pragma unroll
        for (int c = 0; c < 8; c++) o_acc[i][c] = 0.f;
    }

    const int ntmax = 2 * qt + 1;
    for (int nt = 0; nt <= ntmax; nt++) {
        const float* kb = g_k + (size_t)(b * SS + nt * 64) * 512 + kvh * HDIM;
        const float* vb = g_v + (size_t)(b * SS + nt * 64) * 512 + kvh * HDIM;

        __syncthreads();
#pragma unroll
        for (int tt = 0; tt < 8; tt++) {
            int f4 = tid + tt * 256;
            int row = f4 >> 5, d4 = f4 & 31;
            float4 k4 = *(const float4*)(kb + (size_t)row * 512 + d4 * 4);
            Kt[(d4*4+0)*KTP + row] = k4.x;
            Kt[(d4*4+1)*KTP + row] = k4.y;
            Kt[(d4*4+2)*KTP + row] = k4.z;
            Kt[(d4*4+3)*KTP + row] = k4.w;
            *(float4*)&Vs[row * 128 + d4 * 4] =
                *(const float4*)(vb + (size_t)row * 512 + d4 * 4);
        }
        __syncthreads();

        float s[8][4];
#pragma unroll
        for (int i = 0; i < 8; i++)
#pragma unroll
            for (int j = 0; j < 4; j++) s[i][j] = 0.f;

#pragma unroll 4
        for (int d = 0; d < 128; d++) {
            float4 q0 = *(const float4*)&Qt[d*QTP + ty*8];
            float4 q1 = *(const float4*)&Qt[d*QTP + ty*8 + 4];
            float4 kv = *(const float4*)&Kt[d*KTP + tx*4];
            float qa[8] = {q0.x,q0.y,q0.z,q0.w, q1.x,q1.y,q1.z,q1.w};
            float ka[4] = {kv.x,kv.y,kv.z,kv.w};
#pragma unroll
            for (int i = 0; i < 8; i++)
#pragma unroll
                for (int j = 0; j < 4; j++)
                    s[i][j] = fmaf(qa[i], ka[j], s[i][j]);
        }

        const bool edge = (nt >= 2 * qt);
        const int colbase = (nt - 2 * qt) * 64 + tx * 4;

#pragma unroll
        for (int i = 0; i < 8; i++) {
            int lrow = ty * 8 + i;
#pragma unroll
            for (int j = 0; j < 4; j++) {
                float val = s[i][j] * QK_SCALE;
                if (edge && (colbase + j > lrow)) val = -1e30f;
                s[i][j] = val;
            }
            float mt = fmaxf(fmaxf(s[i][0], s[i][1]), fmaxf(s[i][2], s[i][3]));
#pragma unroll
            for (int off = 8; off > 0; off >>= 1)
                mt = fmaxf(mt, __shfl_xor_sync(0xffffffffu, mt, off));
            float mnew  = fmaxf(m_i[i], mt);
            float alpha = __expf(m_i[i] - mnew);
            m_i[i] = mnew;
            float p0 = __expf(s[i][0] - mnew);
            float p1 = __expf(s[i][1] - mnew);
            float p2 = __expf(s[i][2] - mnew);
            float p3 = __expf(s[i][3] - mnew);
            float rs = (p0 + p1) + (p2 + p3);
#pragma unroll
            for (int off = 8; off > 0; off >>= 1)
                rs += __shfl_xor_sync(0xffffffffu, rs, off);
            l_i[i] = l_i[i] * alpha + rs;
#pragma unroll
            for (int c = 0; c < 8; c++) o_acc[i][c] *= alpha;
            int pr = lrow * KTP + tx * 4;
            Ps[pr+0] = p0; Ps[pr+1] = p1; Ps[pr+2] = p2; Ps[pr+3] = p3;
        }
        __syncthreads();

#pragma unroll 2
        for (int kc = 0; kc < 64; kc++) {
            float4 va = *(const float4*)&Vs[kc*128 + tx*4];
            float4 vb4 = *(const float4*)&Vs[kc*128 + 64 + tx*4];
#pragma unroll
            for (int i = 0; i < 8; i++) {
                float pp = Ps[(ty*8+i)*KTP + kc];
                o_acc[i][0] = fmaf(pp, va.x,  o_acc[i][0]);
                o_acc[i][1] = fmaf(pp, va.y,  o_acc[i][1]);
                o_acc[i][2] = fmaf(pp, va.z,  o_acc[i][2]);
                o_acc[i][3] = fmaf(pp, va.w,  o_acc[i][3]);
                o_acc[i][4] = fmaf(pp, vb4.x, o_acc[i][4]);
                o_acc[i][5] = fmaf(pp, vb4.y, o_acc[i][5]);
                o_acc[i][6] = fmaf(pp, vb4.z, o_acc[i][6]);
                o_acc[i][7] = fmaf(pp, vb4.w, o_acc[i][7]);
            }
        }
    }

    float* obase = g_o + (size_t)qrow0 * DD + h * HDIM;
#pragma unroll
    for (int i = 0; i < 8; i++) {
        int r = ty * 8 + i;
        float inv = 1.0f / l_i[i];
        float4 r0 = make_float4(o_acc[i][0]*inv, o_acc[i][1]*inv,
                                o_acc[i][2]*inv, o_acc[i][3]*inv);
        float4 r1 = make_float4(o_acc[i][4]*inv, o_acc[i][5]*inv,
                                o_acc[i][6]*inv, o_acc[i][7]*inv);
        *(float4*)(obase + (size_t)r * DD + tx*4)      = r0;
        *(float4*)(obase + (size_t)r * DD + 64 + tx*4) = r1;
    }
}

// =====================================================================
// launch
// =====================================================================
extern "C" void kernel_launch(void* const* d_in, const int* in_sizes, int n_in,
                              void* d_out, int out_size)
{
    const float* x    = (const float*)d_in[0];
    const float* wq_w = (const float*)d_in[1];
    const float* wq_b = (const float*)d_in[2];
    const float* wk_w = (const float*)d_in[3];
    const float* wk_b = (const float*)d_in[4];
    const float* wv_w = (const float*)d_in[5];
    const float* wv_b = (const float*)d_in[6];
    const float* wo_w = (const float*)d_in[7];
    const float* fcos = (const float*)d_in[10];
    const float* fsin = (const float*)d_in[11];
    const int*   spos = (const int*)d_in[13];
    float* out = (float*)d_out;

    cudaFuncSetAttribute(qkv_kernel,
                         cudaFuncAttributeMaxDynamicSharedMemorySize, GEMM_SMEM_BYTES);
    cudaFuncSetAttribute(oproj_kernel,
                         cudaFuncAttributeMaxDynamicSharedMemorySize, GEMM_SMEM_BYTES);
    cudaFuncSetAttribute(attn_kernel,
                         cudaFuncAttributeMaxDynamicSharedMemorySize, ATTN_SMEM_BYTES);

    // resolve symbol addresses (host-side, capture-safe)
    float *p_xr, *p_wqkv, *p_wor, *p_o;
    cudaGetSymbolAddress((void**)&p_xr,   g_xr);
    cudaGetSymbolAddress((void**)&p_wqkv, g_wqkv);
    cudaGetSymbolAddress((void**)&p_wor,  g_wor);
    cudaGetSymbolAddress((void**)&p_o,    g_o);

    // tf32 pre-round passes
    round_copy_kernel<<<1024, 256>>>(x,    p_xr,   MM * DD / 4);
    round_copy_kernel<<<1024, 256>>>(wq_w, p_wqkv, (HH*HDIM) * DD / 4);
    round_copy_kernel<<<256,  256>>>(wk_w, p_wqkv + (size_t)(HH*HDIM) * DD, 512 * DD / 4);
    round_copy_kernel<<<256,  256>>>(wv_w, p_wqkv + (size_t)(HH*HDIM + 512) * DD, 512 * DD / 4);
    round_copy_kernel<<<1024, 256>>>(wo_w, p_wor,  DD * DD / 4);

    qkv_kernel<<<dim3(32, 36), 128, GEMM_SMEM_BYTES>>>(wq_b, wk_b, wv_b);

    int pairs = MM * HH * 64 + MM * KVH * 64;
    rope_kernel<<<(pairs + 255) / 256, 256>>>(fcos, fsin, spos);

    attn_kernel<<<dim3(16, 28, 2), 256, ATTN_SMEM_BYTES>>>();

    // round attention output in place, then O-projection
    round_copy_kernel<<<1024, 256>>>(p_o, p_o, MM * DD / 4);
    oproj_kernel<<<dim3(32, 28), 128, GEMM_SMEM_BYTES>>>(out);
}

// round 6
// speedup vs baseline: 1.1756x; 1.1756x over previous
#include <cuda_runtime.h>
#include <cstdint>

// ---------------- problem constants ----------------
#define BB 2
#define SS 2048
#define DD 3584
#define HH 28
#define KVH 4
#define HDIM 128
#define NREP 7
#define MM (BB*SS)            // 4096
#define QK_SCALE 0.08838834764831845f
#define KITERS (DD/16)        // 224

// ---------------- scratch ----------------
__device__ float g_q[(size_t)MM * DD];
__device__ float g_k[(size_t)MM * 512];
__device__ float g_v[(size_t)MM * 512];
__device__ float g_o[(size_t)MM * DD];

// ---------------- helpers ----------------
__device__ __forceinline__ uint32_t f2tf32(float f) {
    uint32_t u;
    asm("cvt.rna.tf32.f32 %0, %1;" : "=r"(u) : "f"(f));
    return u;
}
__device__ __forceinline__ void mma_tf32(float c[4],
                                         uint32_t a0, uint32_t a1, uint32_t a2, uint32_t a3,
                                         uint32_t b0, uint32_t b1) {
    asm volatile(
        "mma.sync.aligned.m16n8k8.row.col.f32.tf32.tf32.f32 "
        "{%0,%1,%2,%3}, {%4,%5,%6,%7}, {%8,%9}, {%0,%1,%2,%3};"
        : "+f"(c[0]), "+f"(c[1]), "+f"(c[2]), "+f"(c[3])
        : "r"(a0), "r"(a1), "r"(a2), "r"(a3), "r"(b0), "r"(b1));
}
__device__ __forceinline__ void cp16(uint32_t s, const float* g) {
    asm volatile("cp.async.cg.shared.global [%0], [%1], 16;" :: "r"(s), "l"(g));
}

// =====================================================================
// TF32 TN GEMM: C[128,128] = A[128,K] * W[128,K]^T (+bias), K=3584.
// 256 thr = 8 warps (2m x 4n), warp tile 64x32, BK=16, 3-stage cp.async.
// launch_bounds(256,2) -> 2 CTAs/SM -> 16 warps/SM (4 per SMSP).
// smem rows padded to 20 words -> conflict-free fragment LDS.
// =====================================================================
#define BKP 20
#define A_WORDS (128*BKP)                  // 2560
#define STG_WORDS (2*A_WORDS)              // 5120
#define NSTG 3
#define GEMM_SMEM_BYTES (NSTG*STG_WORDS*4) // 61440

__device__ __forceinline__ void gemm_tile(
    const float* __restrict__ A,           // (m0,0), ld = DD
    const float* __restrict__ W,           // (n0,0), ld = DD
    const float* __restrict__ bias,
    float* __restrict__ C, int ldc)
{
    extern __shared__ float smf[];
    uint32_t sbase = (uint32_t)__cvta_generic_to_shared(smf);

    const int tid  = threadIdx.x;
    const int warp = tid >> 5, lane = tid & 31;
    const int wm = warp >> 2, wn = warp & 3;       // 2 x 4 warp grid
    const int g = lane >> 2, t = lane & 3;

    const int r0 = tid >> 2;                       // 0..63
    const int ck = (tid & 3) * 4;
    const float* Ag = A + (size_t)r0 * DD + ck;
    const float* Wg = W + (size_t)r0 * DD + ck;
    const uint32_t soff = (uint32_t)(r0 * BKP + ck) * 4;

    auto issue = [&](int stage, int it) {
        uint32_t sa = sbase + (uint32_t)stage * (STG_WORDS * 4) + soff;
        const float* ag = Ag + it * 16;
        const float* wg = Wg + it * 16;
        cp16(sa,                          ag);
        cp16(sa + (uint32_t)(64*BKP)*4,   ag + (size_t)64 * DD);
        uint32_t sb = sa + A_WORDS * 4;
        cp16(sb,                          wg);
        cp16(sb + (uint32_t)(64*BKP)*4,   wg + (size_t)64 * DD);
        asm volatile("cp.async.commit_group;");
    };

    float acc[4][4][4];
#pragma unroll
    for (int mi = 0; mi < 4; mi++)
#pragma unroll
        for (int nj = 0; nj < 4; nj++)
#pragma unroll
            for (int c = 0; c < 4; c++) acc[mi][nj][c] = 0.f;

    issue(0, 0);
    issue(1, 1);

    int stage = 0;
    for (int it = 0; it < KITERS; it++) {
        if (it + 2 < KITERS) {
            asm volatile("cp.async.wait_group 1;");
        } else {
            asm volatile("cp.async.wait_group 0;");
        }
        __syncthreads();
        if (it + 2 < KITERS) {
            int ns = stage + 2; if (ns >= NSTG) ns -= NSTG;
            issue(ns, it + 2);
        }
        const float* ab = smf + stage * STG_WORDS;
        const float* bb = ab + A_WORDS;

#pragma unroll
        for (int kk = 0; kk < 16; kk += 8) {
            uint32_t af[4][4], bf[4][2];
#pragma unroll
            for (int mi = 0; mi < 4; mi++) {
                int row = wm * 64 + mi * 16 + g;
                af[mi][0] = f2tf32(ab[row * BKP + kk + t]);
                af[mi][1] = f2tf32(ab[(row + 8) * BKP + kk + t]);
                af[mi][2] = f2tf32(ab[row * BKP + kk + t + 4]);
                af[mi][3] = f2tf32(ab[(row + 8) * BKP + kk + t + 4]);
            }
#pragma unroll
            for (int nj = 0; nj < 4; nj++) {
                int rb = wn * 32 + nj * 8 + g;
                bf[nj][0] = f2tf32(bb[rb * BKP + kk + t]);
                bf[nj][1] = f2tf32(bb[rb * BKP + kk + t + 4]);
            }
#pragma unroll
            for (int mi = 0; mi < 4; mi++)
#pragma unroll
                for (int nj = 0; nj < 4; nj++)
                    mma_tf32(acc[mi][nj],
                             af[mi][0], af[mi][1], af[mi][2], af[mi][3],
                             bf[nj][0], bf[nj][1]);
        }
        stage++; if (stage >= NSTG) stage = 0;
    }

#pragma unroll
    for (int mi = 0; mi < 4; mi++) {
        int row = wm * 64 + mi * 16 + g;
#pragma unroll
        for (int nj = 0; nj < 4; nj++) {
            int col = wn * 32 + nj * 8 + 2 * t;
            float b0 = bias ? bias[col] : 0.f;
            float b1 = bias ? bias[col + 1] : 0.f;
            *(float2*)(C + (size_t)row * ldc + col) =
                make_float2(acc[mi][nj][0] + b0, acc[mi][nj][1] + b1);
            *(float2*)(C + (size_t)(row + 8) * ldc + col) =
                make_float2(acc[mi][nj][2] + b0, acc[mi][nj][3] + b1);
        }
    }
}

// Fused QKV projection: grid (32, 36). by<28 -> Q, <32 -> K, else V.
__global__ __launch_bounds__(256, 2) void qkv_kernel(
    const float* __restrict__ x,
    const float* __restrict__ wq, const float* __restrict__ bq,
    const float* __restrict__ wk, const float* __restrict__ bk,
    const float* __restrict__ wv, const float* __restrict__ bv)
{
    int m0 = blockIdx.x * 128;
    int by = blockIdx.y;
    const float* W; const float* bias; float* C; int ldc;
    if (by < 28) {
        W = wq + (size_t)by * 128 * DD;  bias = bq + by * 128;
        C = g_q + (size_t)m0 * DD + by * 128; ldc = DD;
    } else if (by < 32) {
        int nb = by - 28;
        W = wk + (size_t)nb * 128 * DD;  bias = bk + nb * 128;
        C = g_k + (size_t)m0 * 512 + nb * 128; ldc = 512;
    } else {
        int nb = by - 32;
        W = wv + (size_t)nb * 128 * DD;  bias = bv + nb * 128;
        C = g_v + (size_t)m0 * 512 + nb * 128; ldc = 512;
    }
    gemm_tile(x + (size_t)m0 * DD, W, bias, C, ldc);
}

// Output projection: grid (32, 28).
__global__ __launch_bounds__(256, 2) void oproj_kernel(
    const float* __restrict__ wo, float* __restrict__ out)
{
    int m0 = blockIdx.x * 128;
    int n0 = blockIdx.y * 128;
    gemm_tile(g_o + (size_t)m0 * DD, wo + (size_t)n0 * DD, nullptr,
              out + (size_t)m0 * DD + n0, DD);
}

// =====================================================================
// RoPE on g_q and g_k (in place).
// =====================================================================
__global__ __launch_bounds__(256) void rope_kernel(
    const float* __restrict__ cosT, const float* __restrict__ sinT,
    const int* __restrict__ spp)
{
    const int QP = MM * HH * 64;
    const int KP = MM * KVH * 64;
    int idx = blockIdx.x * blockDim.x + threadIdx.x;
    if (idx >= QP + KP) return;
    int sp = spp[0];
    float* buf; int nh; int i2;
    if (idx < QP) { buf = g_q; nh = HH;  i2 = idx; }
    else          { buf = g_k; nh = KVH; i2 = idx - QP; }
    int d2 = i2 & 63;
    int t  = i2 >> 6;
    int h  = t % nh;
    int m  = t / nh;
    int s  = m & (SS - 1);
    int pos = sp + s;
    float c  = cosT[pos * 64 + d2];
    float sn = sinT[pos * 64 + d2];
    size_t off = (size_t)m * (nh * HDIM) + h * HDIM + 2 * d2;
    float2 v = *(float2*)(buf + off);
    float yr = v.x * c - v.y * sn;
    float yi = v.x * sn + v.y * c;
    *(float2*)(buf + off) = make_float2(yr, yi);
}

// =====================================================================
// Flash attention (causal), fp32. BM=128, BN=64, HD=128, 256 thr (16x16).
// (At fp32-FMA roofline; unchanged.)
// =====================================================================
#define QTP 132
#define KTP 68
#define ATTN_SMEM_WORDS (128*QTP + 128*KTP + 64*128 + 128*KTP)
#define ATTN_SMEM_BYTES (ATTN_SMEM_WORDS*4)   // 169984

__global__ __launch_bounds__(256) void attn_kernel()
{
    extern __shared__ float sm[];
    float* Qt = sm;                       // [128 d][132 rows]
    float* Kt = Qt + 128*QTP;             // [128 d][68 rows]
    float* Vs = Kt + 128*KTP;             // [64 rows][128 d]
    float* Ps = Vs + 64*128;              // [128 rows][68 cols]

    const int qt = gridDim.x - 1 - blockIdx.x;
    const int h  = blockIdx.y;
    const int b  = blockIdx.z;
    const int kvh = h / NREP;
    const int tid = threadIdx.x;
    const int ty = tid >> 4, tx = tid & 15;

    const int qrow0 = b * SS + qt * 128;

    {
        const float* qbase = g_q + (size_t)qrow0 * DD + h * HDIM;
#pragma unroll
        for (int tt = 0; tt < 16; tt++) {
            int f4 = tid + tt * 256;
            int row = f4 >> 5, d4 = f4 & 31;
            float4 qv = *(const float4*)(qbase + (size_t)row * DD + d4 * 4);
            Qt[(d4*4+0)*QTP + row] = qv.x;
            Qt[(d4*4+1)*QTP + row] = qv.y;
            Qt[(d4*4+2)*QTP + row] = qv.z;
            Qt[(d4*4+3)*QTP + row] = qv.w;
        }
    }

    float m_i[8], l_i[8], o_acc[8][8];
#pragma unroll
    for (int i = 0; i < 8; i++) {
        m_i[i] = -1e30f; l_i[i] = 0.f;
#pragma unroll
        for (int c = 0; c < 8; c++) o_acc[i][c] = 0.f;
    }

    const int ntmax = 2 * qt + 1;
    for (int nt = 0; nt <= ntmax; nt++) {
        const float* kb = g_k + (size_t)(b * SS + nt * 64) * 512 + kvh * HDIM;
        const float* vb = g_v + (size_t)(b * SS + nt * 64) * 512 + kvh * HDIM;

        __syncthreads();
#pragma unroll
        for (int tt = 0; tt < 8; tt++) {
            int f4 = tid + tt * 256;
            int row = f4 >> 5, d4 = f4 & 31;
            float4 k4 = *(const float4*)(kb + (size_t)row * 512 + d4 * 4);
            Kt[(d4*4+0)*KTP + row] = k4.x;
            Kt[(d4*4+1)*KTP + row] = k4.y;
            Kt[(d4*4+2)*KTP + row] = k4.z;
            Kt[(d4*4+3)*KTP + row] = k4.w;
            *(float4*)&Vs[row * 128 + d4 * 4] =
                *(const float4*)(vb + (size_t)row * 512 + d4 * 4);
        }
        __syncthreads();

        float s[8][4];
#pragma unroll
        for (int i = 0; i < 8; i++)
#pragma unroll
            for (int j = 0; j < 4; j++) s[i][j] = 0.f;

#pragma unroll 4
        for (int d = 0; d < 128; d++) {
            float4 q0 = *(const float4*)&Qt[d*QTP + ty*8];
            float4 q1 = *(const float4*)&Qt[d*QTP + ty*8 + 4];
            float4 kv = *(const float4*)&Kt[d*KTP + tx*4];
            float qa[8] = {q0.x,q0.y,q0.z,q0.w, q1.x,q1.y,q1.z,q1.w};
            float ka[4] = {kv.x,kv.y,kv.z,kv.w};
#pragma unroll
            for (int i = 0; i < 8; i++)
#pragma unroll
                for (int j = 0; j < 4; j++)
                    s[i][j] = fmaf(qa[i], ka[j], s[i][j]);
        }

        const bool edge = (nt >= 2 * qt);
        const int colbase = (nt - 2 * qt) * 64 + tx * 4;

#pragma unroll
        for (int i = 0; i < 8; i++) {
            int lrow = ty * 8 + i;
#pragma unroll
            for (int j = 0; j < 4; j++) {
                float val = s[i][j] * QK_SCALE;
                if (edge && (colbase + j > lrow)) val = -1e30f;
                s[i][j] = val;
            }
            float mt = fmaxf(fmaxf(s[i][0], s[i][1]), fmaxf(s[i][2], s[i][3]));
#pragma unroll
            for (int off = 8; off > 0; off >>= 1)
                mt = fmaxf(mt, __shfl_xor_sync(0xffffffffu, mt, off));
            float mnew  = fmaxf(m_i[i], mt);
            float alpha = __expf(m_i[i] - mnew);
            m_i[i] = mnew;
            float p0 = __expf(s[i][0] - mnew);
            float p1 = __expf(s[i][1] - mnew);
            float p2 = __expf(s[i][2] - mnew);
            float p3 = __expf(s[i][3] - mnew);
            float rs = (p0 + p1) + (p2 + p3);
#pragma unroll
            for (int off = 8; off > 0; off >>= 1)
                rs += __shfl_xor_sync(0xffffffffu, rs, off);
            l_i[i] = l_i[i] * alpha + rs;
#pragma unroll
            for (int c = 0; c < 8; c++) o_acc[i][c] *= alpha;
            int pr = lrow * KTP + tx * 4;
            Ps[pr+0] = p0; Ps[pr+1] = p1; Ps[pr+2] = p2; Ps[pr+3] = p3;
        }
        __syncthreads();

#pragma unroll 2
        for (int kc = 0; kc < 64; kc++) {
            float4 va = *(const float4*)&Vs[kc*128 + tx*4];
            float4 vb4 = *(const float4*)&Vs[kc*128 + 64 + tx*4];
#pragma unroll
            for (int i = 0; i < 8; i++) {
                float pp = Ps[(ty*8+i)*KTP + kc];
                o_acc[i][0] = fmaf(pp, va.x,  o_acc[i][0]);
                o_acc[i][1] = fmaf(pp, va.y,  o_acc[i][1]);
                o_acc[i][2] = fmaf(pp, va.z,  o_acc[i][2]);
                o_acc[i][3] = fmaf(pp, va.w,  o_acc[i][3]);
                o_acc[i][4] = fmaf(pp, vb4.x, o_acc[i][4]);
                o_acc[i][5] = fmaf(pp, vb4.y, o_acc[i][5]);
                o_acc[i][6] = fmaf(pp, vb4.z, o_acc[i][6]);
                o_acc[i][7] = fmaf(pp, vb4.w, o_acc[i][7]);
            }
        }
    }

    float* obase = g_o + (size_t)qrow0 * DD + h * HDIM;
#pragma unroll
    for (int i = 0; i < 8; i++) {
        int r = ty * 8 + i;
        float inv = 1.0f / l_i[i];
        float4 r0 = make_float4(o_acc[i][0]*inv, o_acc[i][1]*inv,
                                o_acc[i][2]*inv, o_acc[i][3]*inv);
        float4 r1 = make_float4(o_acc[i][4]*inv, o_acc[i][5]*inv,
                                o_acc[i][6]*inv, o_acc[i][7]*inv);
        *(float4*)(obase + (size_t)r * DD + tx*4)      = r0;
        *(float4*)(obase + (size_t)r * DD + 64 + tx*4) = r1;
    }
}

// =====================================================================
// launch
// =====================================================================
extern "C" void kernel_launch(void* const* d_in, const int* in_sizes, int n_in,
                              void* d_out, int out_size)
{
    const float* x    = (const float*)d_in[0];
    const float* wq_w = (const float*)d_in[1];
    const float* wq_b = (const float*)d_in[2];
    const float* wk_w = (const float*)d_in[3];
    const float* wk_b = (const float*)d_in[4];
    const float* wv_w = (const float*)d_in[5];
    const float* wv_b = (const float*)d_in[6];
    const float* wo_w = (const float*)d_in[7];
    const float* fcos = (const float*)d_in[10];
    const float* fsin = (const float*)d_in[11];
    const int*   spos = (const int*)d_in[13];
    float* out = (float*)d_out;

    cudaFuncSetAttribute(qkv_kernel,
                         cudaFuncAttributeMaxDynamicSharedMemorySize, GEMM_SMEM_BYTES);
    cudaFuncSetAttribute(oproj_kernel,
                         cudaFuncAttributeMaxDynamicSharedMemorySize, GEMM_SMEM_BYTES);
    cudaFuncSetAttribute(attn_kernel,
                         cudaFuncAttributeMaxDynamicSharedMemorySize, ATTN_SMEM_BYTES);

    qkv_kernel<<<dim3(32, 36), 256, GEMM_SMEM_BYTES>>>(
        x, wq_w, wq_b, wk_w, wk_b, wv_w, wv_b);

    int pairs = MM * HH * 64 + MM * KVH * 64;
    rope_kernel<<<(pairs + 255) / 256, 256>>>(fcos, fsin, spos);

    attn_kernel<<<dim3(16, 28, 2), 256, ATTN_SMEM_BYTES>>>();

    oproj_kernel<<<dim3(32, 28), 256, GEMM_SMEM_BYTES>>>(wo_w, out);
}

// round 9
// speedup vs baseline: 1.4296x; 1.2160x over previous
#include <cuda_runtime.h>
#include <cstdint>

// ---------------- problem constants ----------------
#define BB 2
#define SS 2048
#define DD 3584
#define HH 28
#define KVH 4
#define HDIM 128
#define NREP 7
#define MM (BB*SS)            // 4096
#define QK_SCALE 0.08838834764831845f
#define KITERS (DD/16)        // 224

// ---------------- scratch ----------------
__device__ float g_q[(size_t)MM * DD];
__device__ float g_k[(size_t)MM * 512];
__device__ float g_v[(size_t)MM * 512];
__device__ float g_o[(size_t)MM * DD];

// ---------------- helpers ----------------
__device__ __forceinline__ uint32_t pack_h2(float lo, float hi) {
    uint32_t r;
    asm("cvt.rn.f16x2.f32 %0, %1, %2;" : "=r"(r) : "f"(hi), "f"(lo));
    return r;   // low half = lo, high half = hi
}
__device__ __forceinline__ uint32_t pack_h2v(float2 v) { return pack_h2(v.x, v.y); }

__device__ __forceinline__ void mma_f16(float c[4],
                                        uint32_t a0, uint32_t a1, uint32_t a2, uint32_t a3,
                                        uint32_t b0, uint32_t b1) {
    asm volatile(
        "mma.sync.aligned.m16n8k16.row.col.f32.f16.f16.f32 "
        "{%0,%1,%2,%3}, {%4,%5,%6,%7}, {%8,%9}, {%0,%1,%2,%3};"
        : "+f"(c[0]), "+f"(c[1]), "+f"(c[2]), "+f"(c[3])
        : "r"(a0), "r"(a1), "r"(a2), "r"(a3), "r"(b0), "r"(b1));
}
__device__ __forceinline__ void cp16(uint32_t s, const float* g) {
    asm volatile("cp.async.cg.shared.global [%0], [%1], 16;" :: "r"(s), "l"(g));
}

// =====================================================================
// FP16 TN GEMM: C[128,128] = A[128,K] * W[128,K]^T (+bias), K=3584.
// fp32 tiles in smem (3-stage cp.async); fragments converted to fp16 at
// load (LDS.64 + cvt.rn.f16x2), mma.m16n8k16 (2x MACs/instr vs tf32-k8).
// 256 thr = 8 warps (2m x 4n), warp tile 64x32, BK=16.
// Row pad = 24 words -> conflict-free float2 fragment loads.
// launch_bounds(256,2) -> 2 CTAs/SM.
// =====================================================================
#define BKP 24
#define A_WORDS (128*BKP)                  // 3072
#define STG_WORDS (2*A_WORDS)              // 6144
#define NSTG 3
#define GEMM_SMEM_BYTES (NSTG*STG_WORDS*4) // 73728

__device__ __forceinline__ void gemm_tile(
    const float* __restrict__ A,           // (m0,0), ld = DD
    const float* __restrict__ W,           // (n0,0), ld = DD
    const float* __restrict__ bias,
    float* __restrict__ C, int ldc)
{
    extern __shared__ float smf[];
    uint32_t sbase = (uint32_t)__cvta_generic_to_shared(smf);

    const int tid  = threadIdx.x;
    const int warp = tid >> 5, lane = tid & 31;
    const int wm = warp >> 2, wn = warp & 3;       // 2 x 4 warp grid
    const int g = lane >> 2, t = lane & 3;

    const int r0 = tid >> 2;                       // 0..63
    const int ck = (tid & 3) * 4;
    const float* Ag = A + (size_t)r0 * DD + ck;
    const float* Wg = W + (size_t)r0 * DD + ck;
    const uint32_t soff = (uint32_t)(r0 * BKP + ck) * 4;

    auto issue = [&](int stage, int it) {
        uint32_t sa = sbase + (uint32_t)stage * (STG_WORDS * 4) + soff;
        const float* ag = Ag + it * 16;
        const float* wg = Wg + it * 16;
        cp16(sa,                          ag);
        cp16(sa + (uint32_t)(64*BKP)*4,   ag + (size_t)64 * DD);
        uint32_t sb = sa + A_WORDS * 4;
        cp16(sb,                          wg);
        cp16(sb + (uint32_t)(64*BKP)*4,   wg + (size_t)64 * DD);
        asm volatile("cp.async.commit_group;");
    };

    float acc[4][4][4];
#pragma unroll
    for (int mi = 0; mi < 4; mi++)
#pragma unroll
        for (int nj = 0; nj < 4; nj++)
#pragma unroll
            for (int c = 0; c < 4; c++) acc[mi][nj][c] = 0.f;

    issue(0, 0);
    issue(1, 1);

    int stage = 0;
    for (int it = 0; it < KITERS; it++) {
        if (it + 2 < KITERS) {
            asm volatile("cp.async.wait_group 1;");
        } else {
            asm volatile("cp.async.wait_group 0;");
        }
        __syncthreads();
        if (it + 2 < KITERS) {
            int ns = stage + 2; if (ns >= NSTG) ns -= NSTG;
            issue(ns, it + 2);
        }
        const float* ab = smf + stage * STG_WORDS;
        const float* bb = ab + A_WORDS;

        // fp16 fragments for one k16 step
        uint32_t af[4][4], bf[4][2];
#pragma unroll
        for (int mi = 0; mi < 4; mi++) {
            int row = wm * 64 + mi * 16 + g;
            af[mi][0] = pack_h2v(*(const float2*)&ab[row * BKP + 2*t]);
            af[mi][1] = pack_h2v(*(const float2*)&ab[(row + 8) * BKP + 2*t]);
            af[mi][2] = pack_h2v(*(const float2*)&ab[row * BKP + 2*t + 8]);
            af[mi][3] = pack_h2v(*(const float2*)&ab[(row + 8) * BKP + 2*t + 8]);
        }
#pragma unroll
        for (int nj = 0; nj < 4; nj++) {
            int rb = wn * 32 + nj * 8 + g;
            bf[nj][0] = pack_h2v(*(const float2*)&bb[rb * BKP + 2*t]);
            bf[nj][1] = pack_h2v(*(const float2*)&bb[rb * BKP + 2*t + 8]);
        }
#pragma unroll
        for (int mi = 0; mi < 4; mi++)
#pragma unroll
            for (int nj = 0; nj < 4; nj++)
                mma_f16(acc[mi][nj],
                        af[mi][0], af[mi][1], af[mi][2], af[mi][3],
                        bf[nj][0], bf[nj][1]);

        stage++; if (stage >= NSTG) stage = 0;
    }

#pragma unroll
    for (int mi = 0; mi < 4; mi++) {
        int row = wm * 64 + mi * 16 + g;
#pragma unroll
        for (int nj = 0; nj < 4; nj++) {
            int col = wn * 32 + nj * 8 + 2 * t;
            float b0 = bias ? bias[col] : 0.f;
            float b1 = bias ? bias[col + 1] : 0.f;
            *(float2*)(C + (size_t)row * ldc + col) =
                make_float2(acc[mi][nj][0] + b0, acc[mi][nj][1] + b1);
            *(float2*)(C + (size_t)(row + 8) * ldc + col) =
                make_float2(acc[mi][nj][2] + b0, acc[mi][nj][3] + b1);
        }
    }
}

// Fused QKV projection: grid (32, 36). by<28 -> Q, <32 -> K, else V.
__global__ __launch_bounds__(256, 2) void qkv_kernel(
    const float* __restrict__ x,
    const float* __restrict__ wq, const float* __restrict__ bq,
    const float* __restrict__ wk, const float* __restrict__ bk,
    const float* __restrict__ wv, const float* __restrict__ bv)
{
    int m0 = blockIdx.x * 128;
    int by = blockIdx.y;
    const float* W; const float* bias; float* C; int ldc;
    if (by < 28) {
        W = wq + (size_t)by * 128 * DD;  bias = bq + by * 128;
        C = g_q + (size_t)m0 * DD + by * 128; ldc = DD;
    } else if (by < 32) {
        int nb = by - 28;
        W = wk + (size_t)nb * 128 * DD;  bias = bk + nb * 128;
        C = g_k + (size_t)m0 * 512 + nb * 128; ldc = 512;
    } else {
        int nb = by - 32;
        W = wv + (size_t)nb * 128 * DD;  bias = bv + nb * 128;
        C = g_v + (size_t)m0 * 512 + nb * 128; ldc = 512;
    }
    gemm_tile(x + (size_t)m0 * DD, W, bias, C, ldc);
}

// Output projection: grid (32, 28).
__global__ __launch_bounds__(256, 2) void oproj_kernel(
    const float* __restrict__ wo, float* __restrict__ out)
{
    int m0 = blockIdx.x * 128;
    int n0 = blockIdx.y * 128;
    gemm_tile(g_o + (size_t)m0 * DD, wo + (size_t)n0 * DD, nullptr,
              out + (size_t)m0 * DD + n0, DD);
}

// =====================================================================
// RoPE on g_q and g_k (in place).
// =====================================================================
__global__ __launch_bounds__(256) void rope_kernel(
    const float* __restrict__ cosT, const float* __restrict__ sinT,
    const int* __restrict__ spp)
{
    const int QP = MM * HH * 64;
    const int KP = MM * KVH * 64;
    int idx = blockIdx.x * blockDim.x + threadIdx.x;
    if (idx >= QP + KP) return;
    int sp = spp[0];
    float* buf; int nh; int i2;
    if (idx < QP) { buf = g_q; nh = HH;  i2 = idx; }
    else          { buf = g_k; nh = KVH; i2 = idx - QP; }
    int d2 = i2 & 63;
    int t  = i2 >> 6;
    int h  = t % nh;
    int m  = t / nh;
    int s  = m & (SS - 1);
    int pos = sp + s;
    float c  = cosT[pos * 64 + d2];
    float sn = sinT[pos * 64 + d2];
    size_t off = (size_t)m * (nh * HDIM) + h * HDIM + 2 * d2;
    float2 v = *(float2*)(buf + off);
    float yr = v.x * c - v.y * sn;
    float yi = v.x * sn + v.y * c;
    *(float2*)(buf + off) = make_float2(yr, yi);
}

// =====================================================================
// Flash attention (causal), fp32. BM=128, BN=64, HD=128, 256 thr (16x16).
// (Known-good fp32 version; unchanged this round.)
// =====================================================================
#define QTP 132
#define KTP 68
#define ATTN_SMEM_WORDS (128*QTP + 128*KTP + 64*128 + 128*KTP)
#define ATTN_SMEM_BYTES (ATTN_SMEM_WORDS*4)   // 169984

__global__ __launch_bounds__(256) void attn_kernel()
{
    extern __shared__ float sm[];
    float* Qt = sm;                       // [128 d][132 rows]
    float* Kt = Qt + 128*QTP;             // [128 d][68 rows]
    float* Vs = Kt + 128*KTP;             // [64 rows][128 d]
    float* Ps = Vs + 64*128;              // [128 rows][68 cols]

    const int qt = gridDim.x - 1 - blockIdx.x;
    const int h  = blockIdx.y;
    const int b  = blockIdx.z;
    const int kvh = h / NREP;
    const int tid = threadIdx.x;
    const int ty = tid >> 4, tx = tid & 15;

    const int qrow0 = b * SS + qt * 128;

    {
        const float* qbase = g_q + (size_t)qrow0 * DD + h * HDIM;
#pragma unroll
        for (int tt = 0; tt < 16; tt++) {
            int f4 = tid + tt * 256;
            int row = f4 >> 5, d4 = f4 & 31;
            float4 qv = *(const float4*)(qbase + (size_t)row * DD + d4 * 4);
            Qt[(d4*4+0)*QTP + row] = qv.x;
            Qt[(d4*4+1)*QTP + row] = qv.y;
            Qt[(d4*4+2)*QTP + row] = qv.z;
            Qt[(d4*4+3)*QTP + row] = qv.w;
        }
    }

    float m_i[8], l_i[8], o_acc[8][8];
#pragma unroll
    for (int i = 0; i < 8; i++) {
        m_i[i] = -1e30f; l_i[i] = 0.f;
#pragma unroll
        for (int c = 0; c < 8; c++) o_acc[i][c] = 0.f;
    }

    const int ntmax = 2 * qt + 1;
    for (int nt = 0; nt <= ntmax; nt++) {
        const float* kb = g_k + (size_t)(b * SS + nt * 64) * 512 + kvh * HDIM;
        const float* vb = g_v + (size_t)(b * SS + nt * 64) * 512 + kvh * HDIM;

        __syncthreads();
#pragma unroll
        for (int tt = 0; tt < 8; tt++) {
            int f4 = tid + tt * 256;
            int row = f4 >> 5, d4 = f4 & 31;
            float4 k4 = *(const float4*)(kb + (size_t)row * 512 + d4 * 4);
            Kt[(d4*4+0)*KTP + row] = k4.x;
            Kt[(d4*4+1)*KTP + row] = k4.y;
            Kt[(d4*4+2)*KTP + row] = k4.z;
            Kt[(d4*4+3)*KTP + row] = k4.w;
            *(float4*)&Vs[row * 128 + d4 * 4] =
                *(const float4*)(vb + (size_t)row * 512 + d4 * 4);
        }
        __syncthreads();

        float s[8][4];
#pragma unroll
        for (int i = 0; i < 8; i++)
#pragma unroll
            for (int j = 0; j < 4; j++) s[i][j] = 0.f;

#pragma unroll 4
        for (int d = 0; d < 128; d++) {
            float4 q0 = *(const float4*)&Qt[d*QTP + ty*8];
            float4 q1 = *(const float4*)&Qt[d*QTP + ty*8 + 4];
            float4 kv = *(const float4*)&Kt[d*KTP + tx*4];
            float qa[8] = {q0.x,q0.y,q0.z,q0.w, q1.x,q1.y,q1.z,q1.w};
            float ka[4] = {kv.x,kv.y,kv.z,kv.w};
#pragma unroll
            for (int i = 0; i < 8; i++)
#pragma unroll
                for (int j = 0; j < 4; j++)
                    s[i][j] = fmaf(qa[i], ka[j], s[i][j]);
        }

        const bool edge = (nt >= 2 * qt);
        const int colbase = (nt - 2 * qt) * 64 + tx * 4;

#pragma unroll
        for (int i = 0; i < 8; i++) {
            int lrow = ty * 8 + i;
#pragma unroll
            for (int j = 0; j < 4; j++) {
                float val = s[i][j] * QK_SCALE;
                if (edge && (colbase + j > lrow)) val = -1e30f;
                s[i][j] = val;
            }
            float mt = fmaxf(fmaxf(s[i][0], s[i][1]), fmaxf(s[i][2], s[i][3]));
#pragma unroll
            for (int off = 8; off > 0; off >>= 1)
                mt = fmaxf(mt, __shfl_xor_sync(0xffffffffu, mt, off));
            float mnew  = fmaxf(m_i[i], mt);
            float alpha = __expf(m_i[i] - mnew);
            m_i[i] = mnew;
            float p0 = __expf(s[i][0] - mnew);
            float p1 = __expf(s[i][1] - mnew);
            float p2 = __expf(s[i][2] - mnew);
            float p3 = __expf(s[i][3] - mnew);
            float rs = (p0 + p1) + (p2 + p3);
#pragma unroll
            for (int off = 8; off > 0; off >>= 1)
                rs += __shfl_xor_sync(0xffffffffu, rs, off);
            l_i[i] = l_i[i] * alpha + rs;
#pragma unroll
            for (int c = 0; c < 8; c++) o_acc[i][c] *= alpha;
            int pr = lrow * KTP + tx * 4;
            Ps[pr+0] = p0; Ps[pr+1] = p1; Ps[pr+2] = p2; Ps[pr+3] = p3;
        }
        __syncthreads();

#pragma unroll 2
        for (int kc = 0; kc < 64; kc++) {
            float4 va = *(const float4*)&Vs[kc*128 + tx*4];
            float4 vb4 = *(const float4*)&Vs[kc*128 + 64 + tx*4];
#pragma unroll
            for (int i = 0; i < 8; i++) {
                float pp = Ps[(ty*8+i)*KTP + kc];
                o_acc[i][0] = fmaf(pp, va.x,  o_acc[i][0]);
                o_acc[i][1] = fmaf(pp, va.y,  o_acc[i][1]);
                o_acc[i][2] = fmaf(pp, va.z,  o_acc[i][2]);
                o_acc[i][3] = fmaf(pp, va.w,  o_acc[i][3]);
                o_acc[i][4] = fmaf(pp, vb4.x, o_acc[i][4]);
                o_acc[i][5] = fmaf(pp, vb4.y, o_acc[i][5]);
                o_acc[i][6] = fmaf(pp, vb4.z, o_acc[i][6]);
                o_acc[i][7] = fmaf(pp, vb4.w, o_acc[i][7]);
            }
        }
    }

    float* obase = g_o + (size_t)qrow0 * DD + h * HDIM;
#pragma unroll
    for (int i = 0; i < 8; i++) {
        int r = ty * 8 + i;
        float inv = 1.0f / l_i[i];
        float4 r0 = make_float4(o_acc[i][0]*inv, o_acc[i][1]*inv,
                                o_acc[i][2]*inv, o_acc[i][3]*inv);
        float4 r1 = make_float4(o_acc[i][4]*inv, o_acc[i][5]*inv,
                                o_acc[i][6]*inv, o_acc[i][7]*inv);
        *(float4*)(obase + (size_t)r * DD + tx*4)      = r0;
        *(float4*)(obase + (size_t)r * DD + 64 + tx*4) = r1;
    }
}

// =====================================================================
// launch
// =====================================================================
extern "C" void kernel_launch(void* const* d_in, const int* in_sizes, int n_in,
                              void* d_out, int out_size)
{
    const float* x    = (const float*)d_in[0];
    const float* wq_w = (const float*)d_in[1];
    const float* wq_b = (const float*)d_in[2];
    const float* wk_w = (const float*)d_in[3];
    const float* wk_b = (const float*)d_in[4];
    const float* wv_w = (const float*)d_in[5];
    const float* wv_b = (const float*)d_in[6];
    const float* wo_w = (const float*)d_in[7];
    const float* fcos = (const float*)d_in[10];
    const float* fsin = (const float*)d_in[11];
    const int*   spos = (const int*)d_in[13];
    float* out = (float*)d_out;

    cudaFuncSetAttribute(qkv_kernel,
                         cudaFuncAttributeMaxDynamicSharedMemorySize, GEMM_SMEM_BYTES);
    cudaFuncSetAttribute(oproj_kernel,
                         cudaFuncAttributeMaxDynamicSharedMemorySize, GEMM_SMEM_BYTES);
    cudaFuncSetAttribute(attn_kernel,
                         cudaFuncAttributeMaxDynamicSharedMemorySize, ATTN_SMEM_BYTES);

    qkv_kernel<<<dim3(32, 36), 256, GEMM_SMEM_BYTES>>>(
        x, wq_w, wq_b, wk_w, wk_b, wv_w, wv_b);

    int pairs = MM * HH * 64 + MM * KVH * 64;
    rope_kernel<<<(pairs + 255) / 256, 256>>>(fcos, fsin, spos);

    attn_kernel<<<dim3(16, 28, 2), 256, ATTN_SMEM_BYTES>>>();

    oproj_kernel<<<dim3(32, 28), 256, GEMM_SMEM_BYTES>>>(wo_w, out);
}

// round 10
// speedup vs baseline: 2.4225x; 1.6946x over previous
#include <cuda_runtime.h>
#include <cuda_fp16.h>
#include <cstdint>

// ---------------- problem constants ----------------
#define BB 2
#define SS 2048
#define DD 3584
#define HH 28
#define KVH 4
#define HDIM 128
#define NREP 7
#define MM (BB*SS)            // 4096
#define QK_SCALE 0.08838834764831845f
#define KITERS (DD/16)        // 224

// ---------------- scratch ----------------
__device__ float g_q[(size_t)MM * DD];
__device__ float g_k[(size_t)MM * 512];
__device__ float g_v[(size_t)MM * 512];
__device__ float g_o[(size_t)MM * DD];

// ---------------- helpers ----------------
__device__ __forceinline__ uint32_t pack_h2(float lo, float hi) {
    uint32_t r;
    asm("cvt.rn.f16x2.f32 %0, %1, %2;" : "=r"(r) : "f"(hi), "f"(lo));
    return r;   // low half = lo, high half = hi
}
__device__ __forceinline__ uint32_t pack_h2v(float2 v) { return pack_h2(v.x, v.y); }

__device__ __forceinline__ void mma_f16(float c[4],
                                        uint32_t a0, uint32_t a1, uint32_t a2, uint32_t a3,
                                        uint32_t b0, uint32_t b1) {
    asm volatile(
        "mma.sync.aligned.m16n8k16.row.col.f32.f16.f16.f32 "
        "{%0,%1,%2,%3}, {%4,%5,%6,%7}, {%8,%9}, {%0,%1,%2,%3};"
        : "+f"(c[0]), "+f"(c[1]), "+f"(c[2]), "+f"(c[3])
        : "r"(a0), "r"(a1), "r"(a2), "r"(a3), "r"(b0), "r"(b1));
}
__device__ __forceinline__ void cp16(uint32_t s, const float* g) {
    asm volatile("cp.async.cg.shared.global [%0], [%1], 16;" :: "r"(s), "l"(g));
}
__device__ __forceinline__ void ldsm4(uint32_t& r0, uint32_t& r1, uint32_t& r2,
                                      uint32_t& r3, uint32_t a) {
    asm volatile("ldmatrix.sync.aligned.m8n8.x4.shared.b16 {%0,%1,%2,%3}, [%4];"
                 : "=r"(r0), "=r"(r1), "=r"(r2), "=r"(r3) : "r"(a));
}
__device__ __forceinline__ void ldsm4t(uint32_t& r0, uint32_t& r1, uint32_t& r2,
                                       uint32_t& r3, uint32_t a) {
    asm volatile("ldmatrix.sync.aligned.m8n8.x4.trans.shared.b16 {%0,%1,%2,%3}, [%4];"
                 : "=r"(r0), "=r"(r1), "=r"(r2), "=r"(r3) : "r"(a));
}
// fp32x4 -> fp16 hi pair + residual lo pair
__device__ __forceinline__ void split4(float4 v, uint2& hi, uint2& lo) {
    uint32_t h01 = pack_h2(v.x, v.y), h23 = pack_h2(v.z, v.w);
    float2 fa = __half22float2(*(__half2*)&h01);
    float2 fb = __half22float2(*(__half2*)&h23);
    uint32_t l01 = pack_h2(v.x - fa.x, v.y - fa.y);
    uint32_t l23 = pack_h2(v.z - fb.x, v.w - fb.y);
    hi = make_uint2(h01, h23); lo = make_uint2(l01, l23);
}

// =====================================================================
// FP16 TN GEMM (proven Round-9 engine, unchanged)
// =====================================================================
#define BKP 24
#define A_WORDS (128*BKP)
#define STG_WORDS (2*A_WORDS)
#define NSTG 3
#define GEMM_SMEM_BYTES (NSTG*STG_WORDS*4)

__device__ __forceinline__ void gemm_tile(
    const float* __restrict__ A, const float* __restrict__ W,
    const float* __restrict__ bias, float* __restrict__ C, int ldc)
{
    extern __shared__ float smf[];
    uint32_t sbase = (uint32_t)__cvta_generic_to_shared(smf);

    const int tid  = threadIdx.x;
    const int warp = tid >> 5, lane = tid & 31;
    const int wm = warp >> 2, wn = warp & 3;
    const int g = lane >> 2, t = lane & 3;

    const int r0 = tid >> 2;
    const int ck = (tid & 3) * 4;
    const float* Ag = A + (size_t)r0 * DD + ck;
    const float* Wg = W + (size_t)r0 * DD + ck;
    const uint32_t soff = (uint32_t)(r0 * BKP + ck) * 4;

    auto issue = [&](int stage, int it) {
        uint32_t sa = sbase + (uint32_t)stage * (STG_WORDS * 4) + soff;
        const float* ag = Ag + it * 16;
        const float* wg = Wg + it * 16;
        cp16(sa,                          ag);
        cp16(sa + (uint32_t)(64*BKP)*4,   ag + (size_t)64 * DD);
        uint32_t sb = sa + A_WORDS * 4;
        cp16(sb,                          wg);
        cp16(sb + (uint32_t)(64*BKP)*4,   wg + (size_t)64 * DD);
        asm volatile("cp.async.commit_group;");
    };

    float acc[4][4][4];
#pragma unroll
    for (int mi = 0; mi < 4; mi++)
#pragma unroll
        for (int nj = 0; nj < 4; nj++)
#pragma unroll
            for (int c = 0; c < 4; c++) acc[mi][nj][c] = 0.f;

    issue(0, 0);
    issue(1, 1);

    int stage = 0;
    for (int it = 0; it < KITERS; it++) {
        if (it + 2 < KITERS) {
            asm volatile("cp.async.wait_group 1;");
        } else {
            asm volatile("cp.async.wait_group 0;");
        }
        __syncthreads();
        if (it + 2 < KITERS) {
            int ns = stage + 2; if (ns >= NSTG) ns -= NSTG;
            issue(ns, it + 2);
        }
        const float* ab = smf + stage * STG_WORDS;
        const float* bb = ab + A_WORDS;

        uint32_t af[4][4], bf[4][2];
#pragma unroll
        for (int mi = 0; mi < 4; mi++) {
            int row = wm * 64 + mi * 16 + g;
            af[mi][0] = pack_h2v(*(const float2*)&ab[row * BKP + 2*t]);
            af[mi][1] = pack_h2v(*(const float2*)&ab[(row + 8) * BKP + 2*t]);
            af[mi][2] = pack_h2v(*(const float2*)&ab[row * BKP + 2*t + 8]);
            af[mi][3] = pack_h2v(*(const float2*)&ab[(row + 8) * BKP + 2*t + 8]);
        }
#pragma unroll
        for (int nj = 0; nj < 4; nj++) {
            int rb = wn * 32 + nj * 8 + g;
            bf[nj][0] = pack_h2v(*(const float2*)&bb[rb * BKP + 2*t]);
            bf[nj][1] = pack_h2v(*(const float2*)&bb[rb * BKP + 2*t + 8]);
        }
#pragma unroll
        for (int mi = 0; mi < 4; mi++)
#pragma unroll
            for (int nj = 0; nj < 4; nj++)
                mma_f16(acc[mi][nj],
                        af[mi][0], af[mi][1], af[mi][2], af[mi][3],
                        bf[nj][0], bf[nj][1]);

        stage++; if (stage >= NSTG) stage = 0;
    }

#pragma unroll
    for (int mi = 0; mi < 4; mi++) {
        int row = wm * 64 + mi * 16 + g;
#pragma unroll
        for (int nj = 0; nj < 4; nj++) {
            int col = wn * 32 + nj * 8 + 2 * t;
            float b0 = bias ? bias[col] : 0.f;
            float b1 = bias ? bias[col + 1] : 0.f;
            *(float2*)(C + (size_t)row * ldc + col) =
                make_float2(acc[mi][nj][0] + b0, acc[mi][nj][1] + b1);
            *(float2*)(C + (size_t)(row + 8) * ldc + col) =
                make_float2(acc[mi][nj][2] + b0, acc[mi][nj][3] + b1);
        }
    }
}

__global__ __launch_bounds__(256, 2) void qkv_kernel(
    const float* __restrict__ x,
    const float* __restrict__ wq, const float* __restrict__ bq,
    const float* __restrict__ wk, const float* __restrict__ bk,
    const float* __restrict__ wv, const float* __restrict__ bv)
{
    int m0 = blockIdx.x * 128;
    int by = blockIdx.y;
    const float* W; const float* bias; float* C; int ldc;
    if (by < 28) {
        W = wq + (size_t)by * 128 * DD;  bias = bq + by * 128;
        C = g_q + (size_t)m0 * DD + by * 128; ldc = DD;
    } else if (by < 32) {
        int nb = by - 28;
        W = wk + (size_t)nb * 128 * DD;  bias = bk + nb * 128;
        C = g_k + (size_t)m0 * 512 + nb * 128; ldc = 512;
    } else {
        int nb = by - 32;
        W = wv + (size_t)nb * 128 * DD;  bias = bv + nb * 128;
        C = g_v + (size_t)m0 * 512 + nb * 128; ldc = 512;
    }
    gemm_tile(x + (size_t)m0 * DD, W, bias, C, ldc);
}

__global__ __launch_bounds__(256, 2) void oproj_kernel(
    const float* __restrict__ wo, float* __restrict__ out)
{
    int m0 = blockIdx.x * 128;
    int n0 = blockIdx.y * 128;
    gemm_tile(g_o + (size_t)m0 * DD, wo + (size_t)n0 * DD, nullptr,
              out + (size_t)m0 * DD + n0, DD);
}

// =====================================================================
// RoPE on g_q and g_k (in place). Unchanged.
// =====================================================================
__global__ __launch_bounds__(256) void rope_kernel(
    const float* __restrict__ cosT, const float* __restrict__ sinT,
    const int* __restrict__ spp)
{
    const int QP = MM * HH * 64;
    const int KP = MM * KVH * 64;
    int idx = blockIdx.x * blockDim.x + threadIdx.x;
    if (idx >= QP + KP) return;
    int sp = spp[0];
    float* buf; int nh; int i2;
    if (idx < QP) { buf = g_q; nh = HH;  i2 = idx; }
    else          { buf = g_k; nh = KVH; i2 = idx - QP; }
    int d2 = i2 & 63;
    int t  = i2 >> 6;
    int h  = t % nh;
    int m  = t / nh;
    int s  = m & (SS - 1);
    int pos = sp + s;
    float c  = cosT[pos * 64 + d2];
    float sn = sinT[pos * 64 + d2];
    size_t off = (size_t)m * (nh * HDIM) + h * HDIM + 2 * d2;
    float2 v = *(float2*)(buf + off);
    float yr = v.x * c - v.y * sn;
    float yi = v.x * sn + v.y * c;
    *(float2*)(buf + off) = make_float2(yr, yi);
}

// =====================================================================
// Flash attention (causal) on tensor cores, hi/lo fp16 split (3-term).
// BM=128, BN=64, HD=128, 8 warps (each owns m16 rows).
// smem: Qhi/Qlo[128][136], Khi/Klo[64][136], Vhi/Vlo[64][136] halves.
// K b-frags: ldmatrix.x4; V b-frags: ldmatrix.x4.trans (no transpose pass).
// S and P stay in C-fragment registers (FA2 C->A reuse).
// =====================================================================
#define ROWH 136
#define Q_HI 0
#define Q_LO (128*ROWH)
#define K_HI (256*ROWH)
#define K_LO (320*ROWH)
#define V_HI (384*ROWH)
#define V_LO (448*ROWH)
#define ATT_SMEM_BYTES (512*ROWH*2)    // 139264

__global__ __launch_bounds__(256, 1) void attn_kernel()
{
    extern __shared__ __align__(16) __half smh[];
    uint32_t sbase = (uint32_t)__cvta_generic_to_shared(smh);

    const int qt = gridDim.x - 1 - blockIdx.x;     // heavy tiles first
    const int h  = blockIdx.y;
    const int b  = blockIdx.z;
    const int kvh = h / NREP;
    const int tid = threadIdx.x;
    const int w = tid >> 5, lane = tid & 31;
    const int g = lane >> 2, t = lane & 3;
    const int qrow0 = b * SS + qt * 128;

    // ---- stage Q: fp32 -> hi/lo fp16 smem (once) ----
    {
        const float* qb = g_q + (size_t)qrow0 * DD + h * HDIM;
#pragma unroll
        for (int i = 0; i < 16; i++) {
            int id = tid + i * 256;
            int r = id >> 5, d4 = id & 31;
            float4 v = *(const float4*)(qb + (size_t)r * DD + 4 * d4);
            uint2 hi, lo; split4(v, hi, lo);
            *(uint2*)(smh + Q_HI + r * ROWH + 4 * d4) = hi;
            *(uint2*)(smh + Q_LO + r * ROWH + 4 * d4) = lo;
        }
    }

    // per-lane ldmatrix address components
    const int aRow = w * 16 + (lane & 7) + ((lane & 8) ? 8 : 0);
    const int aCol = (lane & 16) ? 8 : 0;
    const uint32_t qHiA = sbase + (uint32_t)(Q_HI + aRow * ROWH + aCol) * 2;
    const uint32_t qLoA = sbase + (uint32_t)(Q_LO + aRow * ROWH + aCol) * 2;
    const int bRow = (lane & 7) + ((lane & 16) ? 8 : 0);
    const int bCol = (lane & 8) ? 8 : 0;
    const uint32_t kHiA = sbase + (uint32_t)(K_HI + bRow * ROWH + bCol) * 2;
    const uint32_t kLoA = sbase + (uint32_t)(K_LO + bRow * ROWH + bCol) * 2;
    const int vRow = lane & 15;
    const int vCol = (lane & 16) ? 8 : 0;
    const uint32_t vHiA = sbase + (uint32_t)(V_HI + vRow * ROWH + vCol) * 2;
    const uint32_t vLoA = sbase + (uint32_t)(V_LO + vRow * ROWH + vCol) * 2;

    float o[16][4];
#pragma unroll
    for (int dj = 0; dj < 16; dj++)
#pragma unroll
        for (int c = 0; c < 4; c++) o[dj][c] = 0.f;
    float m0 = -1e30f, m1 = -1e30f, l0 = 0.f, l1 = 0.f;

    const int qg0 = qt * 128 + w * 16 + g;    // global q row (c0,c1); +8 for c2,c3
    const int ntmax = 2 * qt + 1;

    for (int nt = 0; nt <= ntmax; nt++) {
        __syncthreads();
        // ---- load K,V tiles -> hi/lo fp16 smem ----
        {
            const float* kb = g_k + (size_t)(b * SS + nt * 64) * 512 + kvh * HDIM;
            const float* vb = g_v + (size_t)(b * SS + nt * 64) * 512 + kvh * HDIM;
#pragma unroll
            for (int i = 0; i < 8; i++) {
                int id = tid + i * 256;
                int r = id >> 5, d4 = id & 31;
                uint2 hi, lo;
                split4(*(const float4*)(kb + (size_t)r * 512 + 4 * d4), hi, lo);
                *(uint2*)(smh + K_HI + r * ROWH + 4 * d4) = hi;
                *(uint2*)(smh + K_LO + r * ROWH + 4 * d4) = lo;
                split4(*(const float4*)(vb + (size_t)r * 512 + 4 * d4), hi, lo);
                *(uint2*)(smh + V_HI + r * ROWH + 4 * d4) = hi;
                *(uint2*)(smh + V_LO + r * ROWH + 4 * d4) = lo;
            }
        }
        __syncthreads();

        // ---- S = Q K^T (3-term hi/lo) ----
        float s[8][4];
#pragma unroll
        for (int nj = 0; nj < 8; nj++)
#pragma unroll
            for (int c = 0; c < 4; c++) s[nj][c] = 0.f;

#pragma unroll
        for (int ks = 0; ks < 8; ks++) {
            const uint32_t ko = (uint32_t)(16 * ks) * 2;
            uint32_t ah0, ah1, ah2, ah3, al0, al1, al2, al3;
            ldsm4(ah0, ah1, ah2, ah3, qHiA + ko);
            ldsm4(al0, al1, al2, al3, qLoA + ko);
#pragma unroll
            for (int njp = 0; njp < 4; njp++) {
                const uint32_t no = (uint32_t)(16 * njp * ROWH) * 2;
                uint32_t bh0, bh1, bh2, bh3, bl0, bl1, bl2, bl3;
                ldsm4(bh0, bh1, bh2, bh3, kHiA + no + ko);
                ldsm4(bl0, bl1, bl2, bl3, kLoA + no + ko);
                mma_f16(s[2*njp],   ah0, ah1, ah2, ah3, bh0, bh1);
                mma_f16(s[2*njp],   ah0, ah1, ah2, ah3, bl0, bl1);
                mma_f16(s[2*njp],   al0, al1, al2, al3, bh0, bh1);
                mma_f16(s[2*njp+1], ah0, ah1, ah2, ah3, bh2, bh3);
                mma_f16(s[2*njp+1], ah0, ah1, ah2, ah3, bl2, bl3);
                mma_f16(s[2*njp+1], al0, al1, al2, al3, bh2, bh3);
            }
        }

        // ---- online softmax (registers + quad shuffles) ----
        const bool edge = (nt >= 2 * qt);
        float mx0 = -1e30f, mx1 = -1e30f;
#pragma unroll
        for (int nj = 0; nj < 8; nj++) {
            int kb0 = nt * 64 + nj * 8 + 2 * t;
#pragma unroll
            for (int c = 0; c < 4; c++) {
                float val = s[nj][c] * QK_SCALE;
                if (edge) {
                    int kg = kb0 + (c & 1);
                    int qg = qg0 + ((c >> 1) << 3);
                    if (kg > qg) val = -1e30f;
                }
                s[nj][c] = val;
            }
            mx0 = fmaxf(mx0, fmaxf(s[nj][0], s[nj][1]));
            mx1 = fmaxf(mx1, fmaxf(s[nj][2], s[nj][3]));
        }
        mx0 = fmaxf(mx0, __shfl_xor_sync(0xffffffffu, mx0, 1));
        mx0 = fmaxf(mx0, __shfl_xor_sync(0xffffffffu, mx0, 2));
        mx1 = fmaxf(mx1, __shfl_xor_sync(0xffffffffu, mx1, 1));
        mx1 = fmaxf(mx1, __shfl_xor_sync(0xffffffffu, mx1, 2));
        float nm0 = fmaxf(m0, mx0), nm1 = fmaxf(m1, mx1);
        float al_0 = __expf(m0 - nm0), al_1 = __expf(m1 - nm1);
        m0 = nm0; m1 = nm1;

        float sum0 = 0.f, sum1 = 0.f;
#pragma unroll
        for (int nj = 0; nj < 8; nj++) {
            float p0 = __expf(s[nj][0] - nm0);
            float p1 = __expf(s[nj][1] - nm0);
            float p2 = __expf(s[nj][2] - nm1);
            float p3 = __expf(s[nj][3] - nm1);
            s[nj][0] = p0; s[nj][1] = p1; s[nj][2] = p2; s[nj][3] = p3;
            sum0 += p0 + p1; sum1 += p2 + p3;
        }
        sum0 += __shfl_xor_sync(0xffffffffu, sum0, 1);
        sum0 += __shfl_xor_sync(0xffffffffu, sum0, 2);
        sum1 += __shfl_xor_sync(0xffffffffu, sum1, 1);
        sum1 += __shfl_xor_sync(0xffffffffu, sum1, 2);
        l0 = l0 * al_0 + sum0;
        l1 = l1 * al_1 + sum1;
#pragma unroll
        for (int dj = 0; dj < 16; dj++) {
            o[dj][0] *= al_0; o[dj][1] *= al_0;
            o[dj][2] *= al_1; o[dj][3] *= al_1;
        }

        // ---- O += P V (3-term hi/lo; P from C-frag regs) ----
#pragma unroll
        for (int ks = 0; ks < 4; ks++) {
            const int njA = 2 * ks, njB = 2 * ks + 1;
            uint32_t ph0 = pack_h2(s[njA][0], s[njA][1]);
            uint32_t ph1 = pack_h2(s[njA][2], s[njA][3]);
            uint32_t ph2 = pack_h2(s[njB][0], s[njB][1]);
            uint32_t ph3 = pack_h2(s[njB][2], s[njB][3]);
            float2 f0 = __half22float2(*(__half2*)&ph0);
            float2 f1 = __half22float2(*(__half2*)&ph1);
            float2 f2 = __half22float2(*(__half2*)&ph2);
            float2 f3 = __half22float2(*(__half2*)&ph3);
            uint32_t pl0 = pack_h2(s[njA][0]-f0.x, s[njA][1]-f0.y);
            uint32_t pl1 = pack_h2(s[njA][2]-f1.x, s[njA][3]-f1.y);
            uint32_t pl2 = pack_h2(s[njB][0]-f2.x, s[njB][1]-f2.y);
            uint32_t pl3 = pack_h2(s[njB][2]-f3.x, s[njB][3]-f3.y);
            const uint32_t ko = (uint32_t)(16 * ks * ROWH) * 2;
#pragma unroll
            for (int djp = 0; djp < 8; djp++) {
                const uint32_t dof = (uint32_t)(16 * djp) * 2;
                uint32_t bh0, bh1, bh2, bh3, bl0, bl1, bl2, bl3;
                ldsm4t(bh0, bh1, bh2, bh3, vHiA + ko + dof);
                ldsm4t(bl0, bl1, bl2, bl3, vLoA + ko + dof);
                mma_f16(o[2*djp],   ph0, ph1, ph2, ph3, bh0, bh1);
                mma_f16(o[2*djp],   ph0, ph1, ph2, ph3, bl0, bl1);
                mma_f16(o[2*djp],   pl0, pl1, pl2, pl3, bh0, bh1);
                mma_f16(o[2*djp+1], ph0, ph1, ph2, ph3, bh2, bh3);
                mma_f16(o[2*djp+1], ph0, ph1, ph2, ph3, bl2, bl3);
                mma_f16(o[2*djp+1], pl0, pl1, pl2, pl3, bh2, bh3);
            }
        }
    }

    // ---- epilogue ----
    float inv0 = 1.0f / l0, inv1 = 1.0f / l1;
    float* ob = g_o + (size_t)(qrow0 + w * 16) * DD + h * HDIM;
#pragma unroll
    for (int dj = 0; dj < 16; dj++) {
        int c = dj * 8 + 2 * t;
        *(float2*)(ob + (size_t)g * DD + c) =
            make_float2(o[dj][0] * inv0, o[dj][1] * inv0);
        *(float2*)(ob + (size_t)(g + 8) * DD + c) =
            make_float2(o[dj][2] * inv1, o[dj][3] * inv1);
    }
}

// =====================================================================
// launch
// =====================================================================
extern "C" void kernel_launch(void* const* d_in, const int* in_sizes, int n_in,
                              void* d_out, int out_size)
{
    const float* x    = (const float*)d_in[0];
    const float* wq_w = (const float*)d_in[1];
    const float* wq_b = (const float*)d_in[2];
    const float* wk_w = (const float*)d_in[3];
    const float* wk_b = (const float*)d_in[4];
    const float* wv_w = (const float*)d_in[5];
    const float* wv_b = (const float*)d_in[6];
    const float* wo_w = (const float*)d_in[7];
    const float* fcos = (const float*)d_in[10];
    const float* fsin = (const float*)d_in[11];
    const int*   spos = (const int*)d_in[13];
    float* out = (float*)d_out;

    cudaFuncSetAttribute(qkv_kernel,
                         cudaFuncAttributeMaxDynamicSharedMemorySize, GEMM_SMEM_BYTES);
    cudaFuncSetAttribute(oproj_kernel,
                         cudaFuncAttributeMaxDynamicSharedMemorySize, GEMM_SMEM_BYTES);
    cudaFuncSetAttribute(attn_kernel,
                         cudaFuncAttributeMaxDynamicSharedMemorySize, ATT_SMEM_BYTES);

    qkv_kernel<<<dim3(32, 36), 256, GEMM_SMEM_BYTES>>>(
        x, wq_w, wq_b, wk_w, wk_b, wv_w, wv_b);

    int pairs = MM * HH * 64 + MM * KVH * 64;
    rope_kernel<<<(pairs + 255) / 256, 256>>>(fcos, fsin, spos);

    attn_kernel<<<dim3(16, 28, 2), 256, ATT_SMEM_BYTES>>>();

    oproj_kernel<<<dim3(32, 28), 256, GEMM_SMEM_BYTES>>>(wo_w, out);
}